// round 15
// baseline (speedup 1.0000x reference)
#include <cuda_runtime.h>
#include <cuda_fp16.h>
#include <math.h>
#include <stdint.h>

#define BATCH 64
#define SEQ   512
#define EMB   1024
#define HID   1024
#define G4    4096
#define OUTD  50
#define NCTA  128   // persistent recurrence grid

// ---------------- static device scratch (no cudaMalloc allowed) ----------------
__device__ float g_Gf [(size_t)SEQ * BATCH * G4];
__device__ float g_Gb [(size_t)SEQ * BATCH * G4];
__device__ float g_Hf1[(size_t)SEQ * BATCH * HID];
__device__ float g_Hb1[(size_t)SEQ * BATCH * HID];

// dataflow flags: [layer][dir][step][unit-group]; 8 producers per group.
__device__ unsigned g_flag[2][2][SEQ][8];

// fp16 planes
__device__ __half g_Ah [(size_t)SEQ * BATCH * 1024];
__device__ __half g_Ahf[(size_t)SEQ * BATCH * 1024];
__device__ __half g_Ahb[(size_t)SEQ * BATCH * 1024];
__device__ __half g_B1f[(size_t)SEQ * BATCH * 1024];
__device__ __half g_B1b[(size_t)SEQ * BATCH * 1024];
__device__ __half g_Wh [2][(size_t)G4 * 1024];

// ---------------- embedding gather: writes fp16 A plane directly ----------------
__global__ void embed_kernel(const int* __restrict__ src, const float* __restrict__ emb)
{
    size_t idx = (size_t)blockIdx.x * blockDim.x + threadIdx.x;
    int    e4  = (int)(idx & (EMB / 4 - 1));
    size_t sb  = idx >> 8;
    int    b   = (int)(sb & (BATCH - 1));
    int    s   = (int)(sb >> 6);
    int    tok = src[b * SEQ + s];
    float4 v = ((const float4*)(emb + (size_t)tok * EMB))[e4];
    __half2 h01 = __floats2half2_rn(v.x, v.y);
    __half2 h23 = __floats2half2_rn(v.z, v.w);
    ((uint2*)g_Ah)[idx] = make_uint2(*(unsigned*)&h01, *(unsigned*)&h23);
}

// ---------------- fp32 -> fp16 W conversion ----------------
__global__ void convW_kernel(const float* __restrict__ W, int set)
{
    size_t i = (size_t)blockIdx.x * blockDim.x + threadIdx.x;
    float4 v = ((const float4*)W)[i];
    __half2 h01 = __floats2half2_rn(v.x, v.y);
    __half2 h23 = __floats2half2_rn(v.z, v.w);
    ((uint2*)g_Wh[set])[i] = make_uint2(*(unsigned*)&h01, *(unsigned*)&h23);
}

// ---------------- tensor-core helpers ----------------
__device__ __forceinline__ void ldsm4(unsigned* r, const __half* p)
{
    unsigned a = (unsigned)__cvta_generic_to_shared(p);
    asm volatile("ldmatrix.sync.aligned.m8n8.x4.shared.b16 {%0,%1,%2,%3}, [%4];"
                 : "=r"(r[0]), "=r"(r[1]), "=r"(r[2]), "=r"(r[3]) : "r"(a));
}

__device__ __forceinline__ void mma16816(float* c, const unsigned* a, const unsigned* b)
{
    asm volatile("mma.sync.aligned.m16n8k16.row.col.f32.f16.f16.f32 "
                 "{%0,%1,%2,%3},{%4,%5,%6,%7},{%8,%9},{%0,%1,%2,%3};"
                 : "+f"(c[0]), "+f"(c[1]), "+f"(c[2]), "+f"(c[3])
                 : "r"(a[0]), "r"(a[1]), "r"(a[2]), "r"(a[3]), "r"(b[0]), "r"(b[1]));
}

__device__ __forceinline__ void cp16(void* sdst, const void* gsrc)
{
    unsigned s = (unsigned)__cvta_generic_to_shared(sdst);
    asm volatile("cp.async.cg.shared.global [%0], [%1], 16;" :: "r"(s), "l"(gsrc) : "memory");
}

// ---------------- pipelined fp16 GEMM (validated R11-R14): C = A * W^T + bias ----------------
#define SROW 40
#define STAGE_ELEMS (128 * SROW)
#define STAGE_BYTES (2 * STAGE_ELEMS * 2)
__global__ void __launch_bounds__(256, 2)
gemm_fp16(int a_sel, int set, const float* __restrict__ bias, int c_sel)
{
    extern __shared__ __align__(16) __half smem[];
    float* C = c_sel ? g_Gb : g_Gf;
    const __half* Apl = (a_sel == 0) ? g_Ah : (a_sel == 1) ? g_Ahf : g_Ahb;
    const __half* Wpl = g_Wh[set];

    const int tid    = threadIdx.x;
    const int lane   = tid & 31;
    const int wid    = tid >> 5;
    const int warp_m = wid & 3;
    const int warp_n = wid >> 2;

    const size_t rowA0 = (size_t)blockIdx.y * 128;
    const size_t rowW0 = (size_t)blockIdx.x * 128;

    const int amr = warp_m * 32 + (lane & 15);
    const int akc = (lane >> 4) << 3;
    const int wnr = warp_n * 64 + (lane & 7) + ((lane >> 4) << 3);
    const int wkc = ((lane >> 3) & 1) << 3;

    float acc[2][8][4];
#pragma unroll
    for (int i = 0; i < 2; i++)
#pragma unroll
        for (int j = 0; j < 8; j++)
#pragma unroll
            for (int q = 0; q < 4; q++) acc[i][j][q] = 0.f;

    auto load_stage = [&](int st, int k0) {
        __half* sb = smem + (size_t)st * 2 * STAGE_ELEMS;
#pragma unroll
        for (int i = 0; i < 4; i++) {
            int u = tid + 256 * i;
            int plane = u >> 9;
            int r = (u >> 2) & 127;
            int c = u & 3;
            const __half* src = (plane == 0 ? Apl + (rowA0 + r) * 1024
                                            : Wpl + (rowW0 + r) * 1024) + k0 + c * 8;
            cp16(sb + plane * STAGE_ELEMS + r * SROW + c * 8, src);
        }
        asm volatile("cp.async.commit_group;" ::: "memory");
    };

    load_stage(0, 0);
    load_stage(1, 32);

    for (int cc = 0; cc < 32; cc++) {
        if (cc < 31) { asm volatile("cp.async.wait_group 1;" ::: "memory"); }
        else         { asm volatile("cp.async.wait_group 0;" ::: "memory"); }
        __syncthreads();
        if (cc + 2 < 32) load_stage((cc + 2) % 3, (cc + 2) * 32);

        const __half* sA = smem + (size_t)(cc % 3) * 2 * STAGE_ELEMS;
        const __half* sW = sA + STAGE_ELEMS;

#pragma unroll
        for (int kk = 0; kk < 32; kk += 16) {
            unsigned Af[2][4], Wf[4][4];
#pragma unroll
            for (int mt = 0; mt < 2; mt++)
                ldsm4(Af[mt], sA + (amr + mt * 16) * SROW + akc + kk);
#pragma unroll
            for (int q = 0; q < 4; q++)
                ldsm4(Wf[q], sW + (wnr + q * 16) * SROW + wkc + kk);
#pragma unroll
            for (int mt = 0; mt < 2; mt++)
#pragma unroll
                for (int nt = 0; nt < 8; nt++)
                    mma16816(acc[mt][nt], Af[mt], &Wf[nt >> 1][(nt & 1) * 2]);
        }
        __syncthreads();
    }

    const int rbase = blockIdx.y * 128 + warp_m * 32 + (lane >> 2);
    const int cbase = blockIdx.x * 128 + warp_n * 64 + (lane & 3) * 2;
#pragma unroll
    for (int nt = 0; nt < 8; nt++) {
        int col = cbase + nt * 8;
        float b0 = bias[col], b1 = bias[col + 1];
#pragma unroll
        for (int mt = 0; mt < 2; mt++) {
            int r = rbase + mt * 16;
            *(float2*)(C + (size_t)r * G4 + col) =
                make_float2(acc[mt][nt][0] + b0, acc[mt][nt][1] + b1);
            *(float2*)(C + (size_t)(r + 8) * G4 + col) =
                make_float2(acc[mt][nt][2] + b0, acc[mt][nt][3] + b1);
        }
    }
}

// ---------------- persistent MMA LSTM recurrence (v4: barrier-free dataflow) ----------------
// vs R14: global barrier replaced by per-(step, unit-group) flags. Producers
// never wait; consumers spin only until the h chunk they need is published.
#define WPAD  1032                   // W smem row halfs
#define WHALF (64 * WPAD)            // 66048 halfs
#define APAD  136                    // h smem row halfs (272B, conflict-free ldsm)
#define HBUF  (64 * APAD)            // 8704 halfs per stage
#define SGOFF (WHALF + 3 * HBUF)     // 92160 halfs
#define RSMEM (SGOFF * 2 + 16384)    // 200704 B
__global__ void __launch_bounds__(256, 1)
lstm_recur_kernel(const float* __restrict__ Whh_f, const float* __restrict__ Whh_b,
                  int out_sel)
{
    extern __shared__ __align__(16) __half dsm[];
    __half* sW   = dsm;
    __half* sH   = dsm + WHALF;
    float*  sAcc = (float*)sH;                 // alias: 2 regions of [64][68] fp32
    float*  sG   = (float*)(dsm + SGOFF);      // gate pre-activations, 16KB

    const int d  = blockIdx.x >> 6;
    const int u0 = (blockIdx.x & 63) * 16;
    const int mygrp = (blockIdx.x & 63) >> 3;  // unit-group (8 CTAs each)
    const float*  W  = d ? Whh_b : Whh_f;
    const float*  Gd = d ? g_Gb : g_Gf;
    __half*       Hh = out_sel ? (d ? g_B1b : g_B1f) : (d ? g_Ahb : g_Ahf);
    float*        H32 = out_sel ? (d ? g_Hb1 : g_Hf1) : (float*)0;
    unsigned*     flbase = &g_flag[out_sel][d][0][0];

    const int tid  = threadIdx.x;
    const int lane = tid & 31;
    const int wid  = tid >> 5;
    const int wm   = wid & 1;                  // m32 tile
    const int wn   = (wid >> 1) & 1;           // n32 tile
    const int kh   = wid >> 2;                 // k-half

    // ---- load resident Whh slice -> fp16 smem (once) ----
    {
        int j    = tid >> 2;
        int kseg = (tid & 3) * 256;
        int grow = (j & 3) * 1024 + u0 + (j >> 2);
        const float4* src = (const float4*)(W + (size_t)grow * 1024 + kseg);
        __half* dst = sW + (size_t)j * WPAD + kseg;
#pragma unroll 8
        for (int i = 0; i < 64; i++) {
            float4 v = src[i];
            __half2 a = __floats2half2_rn(v.x, v.y);
            __half2 b = __floats2half2_rn(v.z, v.w);
            ((uint2*)dst)[i] = make_uint2(*(unsigned*)&a, *(unsigned*)&b);
        }
    }
    __syncthreads();

    const int amr = wm * 32 + (lane & 15);
    const int akc = ((lane >> 4) << 3) + kh * 64;
    const int wnr = wn * 32 + (lane & 7) + ((lane >> 4) << 3);
    const int wkc = (((lane >> 3) & 1) << 3) + kh * 64;

    // epilogue mapping: thread -> batch pair (b0,b0+1) x 2 units x 4 gates
    const int et  = tid >> 2;
    const int ep  = tid & 3;
    const int b0  = (et & 7) * 8 + ep * 2;
    const int uu0 = (et >> 3) * 2;

    auto issue_gpre = [&](const float* G) {
#pragma unroll
        for (int i = 0; i < 4; i++) {
            int seg = tid + 256 * i;
            int b   = seg >> 4;
            int gt  = (seg >> 2) & 3;
            int qq  = seg & 3;
            cp16(sG + ((size_t)(b * 4 + gt) * 16 + qq * 4),
                 G + (size_t)b * G4 + gt * 1024 + u0 + qq * 4);
        }
        asm volatile("cp.async.commit_group;" ::: "memory");
    };

    float cst[2][2] = {{0.f, 0.f}, {0.f, 0.f}};

    // prefetch gpre for step 0
    issue_gpre(Gd + (size_t)(d ? SEQ - 1 : 0) * BATCH * G4);

    for (int ts = 0; ts < SEQ; ts++) {
        const int sidx = d ? (SEQ - 1 - ts) : ts;

        float acc[2][4][4];
#pragma unroll
        for (int mt = 0; mt < 2; mt++)
#pragma unroll
            for (int nt = 0; nt < 4; nt++)
#pragma unroll
                for (int q = 0; q < 4; q++) acc[mt][nt][q] = 0.f;

        if (ts > 0) {
            const __half* hin = Hh + (size_t)(d ? sidx + 1 : sidx - 1) * BATCH * HID;
            const volatile unsigned* fl = (const volatile unsigned*)(flbase + (ts - 1) * 8);

            // flag readiness tracking (uniform across CTA; no divergence)
            unsigned readym = 0;
            {
                bool allr = true;
#pragma unroll
                for (int i = 0; i < 8; i++)
                    if (fl[i] != 8u) { allr = false; }
                if (allr) { readym = 0xFFu; __threadfence(); }
            }
            auto ensure = [&](int ch) {
                if (readym & (1u << ch)) return;
                while (fl[ch] != 8u) { }
                __threadfence();
                readym |= 1u << ch;
            };

            auto loadc = [&](int st, int ch) {
                __half* hb = sH + st * HBUF;
#pragma unroll
                for (int i = 0; i < 4; i++) {
                    int seg = tid + 256 * i;             // 0..1023
                    int r = seg >> 4, cs = seg & 15;
                    cp16(hb + r * APAD + cs * 8,
                         hin + (size_t)r * HID + ch * 128 + cs * 8);
                }
                asm volatile("cp.async.commit_group;" ::: "memory");
            };

            ensure(0); loadc(0, 0);
            ensure(1); loadc(1, 1);

            for (int ch = 0; ch < 8; ch++) {
                if (ch < 7) { asm volatile("cp.async.wait_group 1;" ::: "memory"); }
                else        { asm volatile("cp.async.wait_group 0;" ::: "memory"); }
                __syncthreads();
                if (ch + 2 < 8) { ensure(ch + 2); loadc((ch + 2) % 3, ch + 2); }

                const __half* hb = sH + (ch % 3) * HBUF;
#pragma unroll
                for (int kk = 0; kk < 64; kk += 16) {
                    unsigned Af[2][4], Wf[2][4];
#pragma unroll
                    for (int mt = 0; mt < 2; mt++)
                        ldsm4(Af[mt], hb + (amr + mt * 16) * APAD + akc + kk);
                    int kg = ch * 128 + wkc + kk;
#pragma unroll
                    for (int q = 0; q < 2; q++)
                        ldsm4(Wf[q], sW + (size_t)(wnr + q * 16) * WPAD + kg);
#pragma unroll
                    for (int mt = 0; mt < 2; mt++)
#pragma unroll
                        for (int nt = 0; nt < 4; nt++)
                            mma16816(acc[mt][nt], Af[mt], &Wf[nt >> 1][(nt & 1) * 2]);
                }
                // no trailing sync: next iteration's top sync orders stage reuse
            }
        } else {
            asm volatile("cp.async.wait_group 0;" ::: "memory");   // gpre
        }

        // ---- fragments -> smem: k-half kh writes its own [64][68] region ----
        {
            float* sAk = sAcc + (size_t)kh * 64 * 68;
            const int c0 = wn * 32 + (lane & 3) * 2;
#pragma unroll
            for (int mt = 0; mt < 2; mt++) {
                int r0 = wm * 32 + mt * 16 + (lane >> 2);
#pragma unroll
                for (int nt = 0; nt < 4; nt++) {
                    int c = c0 + nt * 8;
                    *(float2*)&sAk[(size_t)r0 * 68 + c] =
                        make_float2(acc[mt][nt][0], acc[mt][nt][1]);
                    *(float2*)&sAk[(size_t)(r0 + 8) * 68 + c] =
                        make_float2(acc[mt][nt][2], acc[mt][nt][3]);
                }
            }
        }
        __syncthreads();

        // ---- activations + c update + coalesced h writes ----
        __half* hw = Hh + (size_t)sidx * BATCH * HID;
        float hv0[2], hv1[2];
#pragma unroll
        for (int us = 0; us < 2; us++) {
            int uu = uu0 + us;
            float4 ga0 = *(const float4*)&sAcc[(size_t)b0 * 68 + uu * 4];
            float4 ga1 = *(const float4*)&sAcc[(size_t)(64 * 68) + (size_t)b0 * 68 + uu * 4];
            float4 gb0 = *(const float4*)&sAcc[(size_t)(b0 + 1) * 68 + uu * 4];
            float4 gb1 = *(const float4*)&sAcc[(size_t)(64 * 68) + (size_t)(b0 + 1) * 68 + uu * 4];
            float gi0 = ga0.x + ga1.x + sG[((size_t)b0 * 4 + 0) * 16 + uu];
            float gf0 = ga0.y + ga1.y + sG[((size_t)b0 * 4 + 1) * 16 + uu];
            float gg0 = ga0.z + ga1.z + sG[((size_t)b0 * 4 + 2) * 16 + uu];
            float go0 = ga0.w + ga1.w + sG[((size_t)b0 * 4 + 3) * 16 + uu];
            float gi1 = gb0.x + gb1.x + sG[((size_t)(b0 + 1) * 4 + 0) * 16 + uu];
            float gf1 = gb0.y + gb1.y + sG[((size_t)(b0 + 1) * 4 + 1) * 16 + uu];
            float gg1 = gb0.z + gb1.z + sG[((size_t)(b0 + 1) * 4 + 2) * 16 + uu];
            float go1 = gb0.w + gb1.w + sG[((size_t)(b0 + 1) * 4 + 3) * 16 + uu];
            float iv0 = 1.f / (1.f + expf(-gi0)), iv1 = 1.f / (1.f + expf(-gi1));
            float fv0 = 1.f / (1.f + expf(-gf0)), fv1 = 1.f / (1.f + expf(-gf1));
            float ov0 = 1.f / (1.f + expf(-go0)), ov1 = 1.f / (1.f + expf(-go1));
            float cn0 = fv0 * cst[us][0] + iv0 * tanhf(gg0);
            float cn1 = fv1 * cst[us][1] + iv1 * tanhf(gg1);
            cst[us][0] = cn0;
            cst[us][1] = cn1;
            hv0[us] = ov0 * tanhf(cn0);
            hv1[us] = ov1 * tanhf(cn1);
        }
        {
            int u = u0 + uu0;
            *(__half2*)&hw[(size_t)b0 * HID + u]       = __floats2half2_rn(hv0[0], hv0[1]);
            *(__half2*)&hw[(size_t)(b0 + 1) * HID + u] = __floats2half2_rn(hv1[0], hv1[1]);
            if (out_sel) {
                float* h32r = H32 + (size_t)sidx * BATCH * HID;
                *(float2*)&h32r[(size_t)b0 * HID + u]       = make_float2(hv0[0], hv0[1]);
                *(float2*)&h32r[(size_t)(b0 + 1) * HID + u] = make_float2(hv1[0], hv1[1]);
            }
        }

        // publish this step's h slice; prefetch next gpre. No global barrier.
        __syncthreads();                       // h writes + sG/sAcc reads complete
        if (ts + 1 < SEQ) {
            if (tid == 0) {
                __threadfence();
                atomicAdd(flbase + ts * 8 + mygrp, 1u);
            }
            issue_gpre(Gd + (size_t)(d ? SEQ - 2 - ts : ts + 1) * BATCH * G4);
        }
    }
}

// ---------------- output projection ----------------
__global__ void __launch_bounds__(256)
out_kernel(const float* __restrict__ Wout, const float* __restrict__ bout,
           float* __restrict__ out)
{
    __shared__ __align__(16) float hf[4][HID];
    __shared__ __align__(16) float hb[4][HID];
    const int tid   = threadIdx.x;
    const int pair0 = blockIdx.x * 4;

    for (int i = tid; i < 2048; i += 256) {
        int p   = i >> 9;
        int rem = i & 511;
        int sb  = pair0 + p;
        int r4  = rem & 255;
        const float* src = (rem < 256 ? g_Hf1 : g_Hb1) + (size_t)sb * HID;
        float4 v = ((const float4*)src)[r4];
        if (rem < 256) ((float4*)hf[p])[r4] = v;
        else           ((float4*)hb[p])[r4] = v;
    }
    __syncthreads();

    int p = tid >> 6;
    int o = tid & 63;
    if (o < OUTD) {
        int sb = pair0 + p;
        int s = sb >> 6, b = sb & 63;
        const float4* w0  = (const float4*)(Wout + (size_t)o * 2 * HID);
        const float4* w1  = w0 + 256;
        const float4* hf4 = (const float4*)hf[p];
        const float4* hb4 = (const float4*)hb[p];
        float acc = 0.f;
#pragma unroll 4
        for (int k = 0; k < 256; k++) {
            float4 a = hf4[k]; float4 w = w0[k];
            acc += a.x*w.x + a.y*w.y + a.z*w.z + a.w*w.w;
        }
#pragma unroll 4
        for (int k = 0; k < 256; k++) {
            float4 a = hb4[k]; float4 w = w1[k];
            acc += a.x*w.x + a.y*w.y + a.z*w.z + a.w*w.w;
        }
        out[((size_t)b * SEQ + s) * OUTD + o] = acc + bout[o];
    }
}

// ---------------- launch sequence ----------------
extern "C" void kernel_launch(void* const* d_in, const int* in_sizes, int n_in,
                              void* d_out, int out_size)
{
    const int*   src   = (const int*)  d_in[0];
    const float* emb   = (const float*)d_in[1];
    const float* Wih_f = (const float*)d_in[2];
    const float* Whh_f = (const float*)d_in[3];
    const float* b_f   = (const float*)d_in[4];
    const float* Wih_b = (const float*)d_in[5];
    const float* Whh_b = (const float*)d_in[6];
    const float* b_b   = (const float*)d_in[7];
    const float* Wout  = (const float*)d_in[8];
    const float* bout  = (const float*)d_in[9];
    float* out = (float*)d_out;
    (void)in_sizes; (void)n_in; (void)out_size;

    cudaFuncSetAttribute(gemm_fp16,
                         cudaFuncAttributeMaxDynamicSharedMemorySize, 3 * STAGE_BYTES);
    cudaFuncSetAttribute(lstm_recur_kernel,
                         cudaFuncAttributeMaxDynamicSharedMemorySize, RSMEM);

    // reset dataflow flags (graph-capturable, no allocation)
    {
        void* fp = nullptr;
        cudaGetSymbolAddress(&fp, g_flag);
        cudaMemsetAsync(fp, 0, sizeof(unsigned) * 2 * 2 * SEQ * 8);
    }

    embed_kernel<<<SEQ * BATCH * (EMB / 4) / 256, 256>>>(src, emb);

    dim3 ggrid(G4 / 128, (SEQ * BATCH) / 128);                 // (32, 256)
    const int convW_blocks = (G4 * 1024 / 4) / 256;            // 4096

    for (int l = 0; l < 2; l++) {
        size_t woff = (size_t)l * G4 * 1024;
        int a_f = (l == 0) ? 0 : 1;
        int a_b = (l == 0) ? 0 : 2;
        convW_kernel<<<convW_blocks, 256>>>(Wih_f + woff, 0);
        convW_kernel<<<convW_blocks, 256>>>(Wih_b + woff, 1);
        gemm_fp16<<<ggrid, 256, 3 * STAGE_BYTES>>>(a_f, 0, b_f + l * G4, 0);
        gemm_fp16<<<ggrid, 256, 3 * STAGE_BYTES>>>(a_b, 1, b_b + l * G4, 1);
        lstm_recur_kernel<<<NCTA, 256, RSMEM>>>(Whh_f + woff, Whh_b + woff, l);
    }

    out_kernel<<<(SEQ * BATCH) / 4, 256>>>(Wout, bout, out);
}

// round 16
// speedup vs baseline: 1.4241x; 1.4241x over previous
#include <cuda_runtime.h>
#include <cuda_fp16.h>
#include <math.h>
#include <stdint.h>

#define BATCH 64
#define SEQ   512
#define EMB   1024
#define HID   1024
#define G4    4096
#define OUTD  50
#define NCTA  128   // persistent recurrence grid
#define NCTAD 64    // CTAs per direction

// ---------------- static device scratch (no cudaMalloc allowed) ----------------
__device__ float g_Gf [(size_t)SEQ * BATCH * G4];
__device__ float g_Gb [(size_t)SEQ * BATCH * G4];
__device__ float g_Hf1[(size_t)SEQ * BATCH * HID];
__device__ float g_Hb1[(size_t)SEQ * BATCH * HID];
__device__ unsigned g_bar2[2][32];   // per-direction barrier counters (line-padded)

// fp16 planes
__device__ __half g_Ah [(size_t)SEQ * BATCH * 1024];
__device__ __half g_Ahf[(size_t)SEQ * BATCH * 1024];
__device__ __half g_Ahb[(size_t)SEQ * BATCH * 1024];
__device__ __half g_B1f[(size_t)SEQ * BATCH * 1024];
__device__ __half g_B1b[(size_t)SEQ * BATCH * 1024];
__device__ __half g_Wh [2][(size_t)G4 * 1024];

// ---------------- per-direction software grid barrier (64 CTAs) ----------------
__device__ __forceinline__ void grid_sync_d(int d)
{
    __syncthreads();
    if (threadIdx.x == 0) {
        __threadfence();
        unsigned ticket = atomicAdd(&g_bar2[d][0], 1u);
        unsigned target = (ticket & ~(unsigned)(NCTAD - 1)) + NCTAD;
        while ((int)(*(volatile unsigned*)&g_bar2[d][0] - target) < 0) { }
        __threadfence();
    }
    __syncthreads();
}

// ---------------- embedding gather: writes fp16 A plane directly ----------------
__global__ void embed_kernel(const int* __restrict__ src, const float* __restrict__ emb)
{
    size_t idx = (size_t)blockIdx.x * blockDim.x + threadIdx.x;
    int    e4  = (int)(idx & (EMB / 4 - 1));
    size_t sb  = idx >> 8;
    int    b   = (int)(sb & (BATCH - 1));
    int    s   = (int)(sb >> 6);
    int    tok = src[b * SEQ + s];
    float4 v = ((const float4*)(emb + (size_t)tok * EMB))[e4];
    __half2 h01 = __floats2half2_rn(v.x, v.y);
    __half2 h23 = __floats2half2_rn(v.z, v.w);
    ((uint2*)g_Ah)[idx] = make_uint2(*(unsigned*)&h01, *(unsigned*)&h23);
}

// ---------------- fp32 -> fp16 W conversion ----------------
__global__ void convW_kernel(const float* __restrict__ W, int set)
{
    size_t i = (size_t)blockIdx.x * blockDim.x + threadIdx.x;
    float4 v = ((const float4*)W)[i];
    __half2 h01 = __floats2half2_rn(v.x, v.y);
    __half2 h23 = __floats2half2_rn(v.z, v.w);
    ((uint2*)g_Wh[set])[i] = make_uint2(*(unsigned*)&h01, *(unsigned*)&h23);
}

// ---------------- tensor-core helpers ----------------
__device__ __forceinline__ void ldsm4(unsigned* r, const __half* p)
{
    unsigned a = (unsigned)__cvta_generic_to_shared(p);
    asm volatile("ldmatrix.sync.aligned.m8n8.x4.shared.b16 {%0,%1,%2,%3}, [%4];"
                 : "=r"(r[0]), "=r"(r[1]), "=r"(r[2]), "=r"(r[3]) : "r"(a));
}

__device__ __forceinline__ void mma16816(float* c, const unsigned* a, const unsigned* b)
{
    asm volatile("mma.sync.aligned.m16n8k16.row.col.f32.f16.f16.f32 "
                 "{%0,%1,%2,%3},{%4,%5,%6,%7},{%8,%9},{%0,%1,%2,%3};"
                 : "+f"(c[0]), "+f"(c[1]), "+f"(c[2]), "+f"(c[3])
                 : "r"(a[0]), "r"(a[1]), "r"(a[2]), "r"(a[3]), "r"(b[0]), "r"(b[1]));
}

__device__ __forceinline__ void cp16(void* sdst, const void* gsrc)
{
    unsigned s = (unsigned)__cvta_generic_to_shared(sdst);
    asm volatile("cp.async.cg.shared.global [%0], [%1], 16;" :: "r"(s), "l"(gsrc) : "memory");
}

// ---------------- pipelined fp16 GEMM (validated R11-R14): C = A * W^T + bias ----------------
#define SROW 40
#define STAGE_ELEMS (128 * SROW)
#define STAGE_BYTES (2 * STAGE_ELEMS * 2)
__global__ void __launch_bounds__(256, 2)
gemm_fp16(int a_sel, int set, const float* __restrict__ bias, int c_sel)
{
    extern __shared__ __align__(16) __half smem[];
    float* C = c_sel ? g_Gb : g_Gf;
    const __half* Apl = (a_sel == 0) ? g_Ah : (a_sel == 1) ? g_Ahf : g_Ahb;
    const __half* Wpl = g_Wh[set];

    const int tid    = threadIdx.x;
    const int lane   = tid & 31;
    const int wid    = tid >> 5;
    const int warp_m = wid & 3;
    const int warp_n = wid >> 2;

    const size_t rowA0 = (size_t)blockIdx.y * 128;
    const size_t rowW0 = (size_t)blockIdx.x * 128;

    const int amr = warp_m * 32 + (lane & 15);
    const int akc = (lane >> 4) << 3;
    const int wnr = warp_n * 64 + (lane & 7) + ((lane >> 4) << 3);
    const int wkc = ((lane >> 3) & 1) << 3;

    float acc[2][8][4];
#pragma unroll
    for (int i = 0; i < 2; i++)
#pragma unroll
        for (int j = 0; j < 8; j++)
#pragma unroll
            for (int q = 0; q < 4; q++) acc[i][j][q] = 0.f;

    auto load_stage = [&](int st, int k0) {
        __half* sb = smem + (size_t)st * 2 * STAGE_ELEMS;
#pragma unroll
        for (int i = 0; i < 4; i++) {
            int u = tid + 256 * i;
            int plane = u >> 9;
            int r = (u >> 2) & 127;
            int c = u & 3;
            const __half* src = (plane == 0 ? Apl + (rowA0 + r) * 1024
                                            : Wpl + (rowW0 + r) * 1024) + k0 + c * 8;
            cp16(sb + plane * STAGE_ELEMS + r * SROW + c * 8, src);
        }
        asm volatile("cp.async.commit_group;" ::: "memory");
    };

    load_stage(0, 0);
    load_stage(1, 32);

    for (int cc = 0; cc < 32; cc++) {
        if (cc < 31) { asm volatile("cp.async.wait_group 1;" ::: "memory"); }
        else         { asm volatile("cp.async.wait_group 0;" ::: "memory"); }
        __syncthreads();
        if (cc + 2 < 32) load_stage((cc + 2) % 3, (cc + 2) * 32);

        const __half* sA = smem + (size_t)(cc % 3) * 2 * STAGE_ELEMS;
        const __half* sW = sA + STAGE_ELEMS;

#pragma unroll
        for (int kk = 0; kk < 32; kk += 16) {
            unsigned Af[2][4], Wf[4][4];
#pragma unroll
            for (int mt = 0; mt < 2; mt++)
                ldsm4(Af[mt], sA + (amr + mt * 16) * SROW + akc + kk);
#pragma unroll
            for (int q = 0; q < 4; q++)
                ldsm4(Wf[q], sW + (wnr + q * 16) * SROW + wkc + kk);
#pragma unroll
            for (int mt = 0; mt < 2; mt++)
#pragma unroll
                for (int nt = 0; nt < 8; nt++)
                    mma16816(acc[mt][nt], Af[mt], &Wf[nt >> 1][(nt & 1) * 2]);
        }
        __syncthreads();
    }

    const int rbase = blockIdx.y * 128 + warp_m * 32 + (lane >> 2);
    const int cbase = blockIdx.x * 128 + warp_n * 64 + (lane & 3) * 2;
#pragma unroll
    for (int nt = 0; nt < 8; nt++) {
        int col = cbase + nt * 8;
        float b0 = bias[col], b1 = bias[col + 1];
#pragma unroll
        for (int mt = 0; mt < 2; mt++) {
            int r = rbase + mt * 16;
            *(float2*)(C + (size_t)r * G4 + col) =
                make_float2(acc[mt][nt][0] + b0, acc[mt][nt][1] + b1);
            *(float2*)(C + (size_t)(r + 8) * G4 + col) =
                make_float2(acc[mt][nt][2] + b0, acc[mt][nt][3] + b1);
        }
    }
}

// ---------------- persistent MMA LSTM recurrence (v5: 512 threads, 4-way k-split) ----------------
// 16 warps: 2m x 2n x 4 k-quarters (32 acc chains/SMSP). Quarters 2,3 reduce
// into quarters 0,1's sAcc regions via smem RMW. Per-direction barrier (R14).
#define WPAD  1032                   // W smem row halfs
#define WHALF (64 * WPAD)            // 66048 halfs
#define APAD  136                    // h smem row halfs (272B, conflict-free ldsm)
#define HBUF  (64 * APAD)            // 8704 halfs per stage
#define SGOFF (WHALF + 3 * HBUF)     // 92160 halfs
#define RSMEM (SGOFF * 2 + 16384)    // 200704 B
__global__ void __launch_bounds__(512, 1)
lstm_recur_kernel(const float* __restrict__ Whh_f, const float* __restrict__ Whh_b,
                  int out_sel)
{
    extern __shared__ __align__(16) __half dsm[];
    __half* sW   = dsm;
    __half* sH   = dsm + WHALF;
    float*  sAcc = (float*)sH;                 // alias: 2 regions of [64][68] fp32
    float*  sG   = (float*)(dsm + SGOFF);      // gate pre-activations, 16KB

    const int d  = blockIdx.x >> 6;
    const int u0 = (blockIdx.x & 63) * 16;
    const float*  W  = d ? Whh_b : Whh_f;
    const float*  Gd = d ? g_Gb : g_Gf;
    __half*       Hh = out_sel ? (d ? g_B1b : g_B1f) : (d ? g_Ahb : g_Ahf);
    float*        H32 = out_sel ? (d ? g_Hb1 : g_Hf1) : (float*)0;

    const int tid  = threadIdx.x;
    const int lane = tid & 31;
    const int wid  = tid >> 5;
    const int wm   = wid & 1;                  // m32 tile
    const int wn   = (wid >> 1) & 1;           // n32 tile
    const int kq   = wid >> 2;                 // k-quarter (0..3)

    // ---- load resident Whh slice -> fp16 smem (once) ----
    {
        int j    = tid >> 3;                   // 0..63
        int kseg = (tid & 7) * 128;
        int grow = (j & 3) * 1024 + u0 + (j >> 2);
        const float4* src = (const float4*)(W + (size_t)grow * 1024 + kseg);
        __half* dst = sW + (size_t)j * WPAD + kseg;
#pragma unroll 8
        for (int i = 0; i < 32; i++) {
            float4 v = src[i];
            __half2 a = __floats2half2_rn(v.x, v.y);
            __half2 b = __floats2half2_rn(v.z, v.w);
            ((uint2*)dst)[i] = make_uint2(*(unsigned*)&a, *(unsigned*)&b);
        }
    }
    __syncthreads();

    const int amr = wm * 32 + (lane & 15);
    const int akc = ((lane >> 4) << 3) + kq * 32;
    const int wnr = wn * 32 + (lane & 7) + ((lane >> 4) << 3);
    const int wkc = (((lane >> 3) & 1) << 3) + kq * 32;

    // epilogue mapping: thread -> batch b x 2 units (uug, uug+1)
    const int eb  = tid >> 3;                  // 0..63
    const int uug = (tid & 7) * 2;             // 0,2,...,14

    auto issue_gpre = [&](const float* G) {
#pragma unroll
        for (int i = 0; i < 2; i++) {
            int seg = tid + 512 * i;           // 0..1023
            int b   = seg >> 4;
            int gt  = (seg >> 2) & 3;
            int qq  = seg & 3;
            cp16(sG + ((size_t)(b * 4 + gt) * 16 + qq * 4),
                 G + (size_t)b * G4 + gt * 1024 + u0 + qq * 4);
        }
        asm volatile("cp.async.commit_group;" ::: "memory");
    };

    float cst[2] = {0.f, 0.f};

    // prefetch gpre for step 0
    issue_gpre(Gd + (size_t)(d ? SEQ - 1 : 0) * BATCH * G4);

    for (int ts = 0; ts < SEQ; ts++) {
        const int sidx = d ? (SEQ - 1 - ts) : ts;

        float acc[2][4][4];
#pragma unroll
        for (int mt = 0; mt < 2; mt++)
#pragma unroll
            for (int nt = 0; nt < 4; nt++)
#pragma unroll
                for (int q = 0; q < 4; q++) acc[mt][nt][q] = 0.f;

        if (ts > 0) {
            const __half* hin = Hh + (size_t)(d ? sidx + 1 : sidx - 1) * BATCH * HID;

            auto loadc = [&](int st, int ch) {
                __half* hb = sH + st * HBUF;
#pragma unroll
                for (int i = 0; i < 2; i++) {
                    int seg = tid + 512 * i;             // 0..1023
                    int r = seg >> 4, cs = seg & 15;
                    cp16(hb + r * APAD + cs * 8,
                         hin + (size_t)r * HID + ch * 128 + cs * 8);
                }
                asm volatile("cp.async.commit_group;" ::: "memory");
            };

            loadc(0, 0);
            loadc(1, 1);

            for (int ch = 0; ch < 8; ch++) {
                if (ch < 7) { asm volatile("cp.async.wait_group 1;" ::: "memory"); }
                else        { asm volatile("cp.async.wait_group 0;" ::: "memory"); }
                __syncthreads();
                if (ch + 2 < 8) loadc((ch + 2) % 3, ch + 2);

                const __half* hb = sH + (ch % 3) * HBUF;
#pragma unroll
                for (int kk = 0; kk < 32; kk += 16) {
                    unsigned Af[2][4], Wf[2][4];
#pragma unroll
                    for (int mt = 0; mt < 2; mt++)
                        ldsm4(Af[mt], hb + (amr + mt * 16) * APAD + akc + kk);
                    int kg = ch * 128 + wkc + kk;
#pragma unroll
                    for (int q = 0; q < 2; q++)
                        ldsm4(Wf[q], sW + (size_t)(wnr + q * 16) * WPAD + kg);
#pragma unroll
                    for (int mt = 0; mt < 2; mt++)
#pragma unroll
                        for (int nt = 0; nt < 4; nt++)
                            mma16816(acc[mt][nt], Af[mt], &Wf[nt >> 1][(nt & 1) * 2]);
                }
                // no trailing sync: next iteration's top sync orders stage reuse
            }
        } else {
            asm volatile("cp.async.wait_group 0;" ::: "memory");   // gpre
        }

        // ---- partials -> smem, two-phase 4->2->epilogue reduction ----
        __syncthreads();                        // all h-stage reads complete
        const int c0 = wn * 32 + (lane & 3) * 2;
        if (kq < 2) {
            float* sAk = sAcc + (size_t)kq * 64 * 68;
#pragma unroll
            for (int mt = 0; mt < 2; mt++) {
                int r0 = wm * 32 + mt * 16 + (lane >> 2);
#pragma unroll
                for (int nt = 0; nt < 4; nt++) {
                    int c = c0 + nt * 8;
                    *(float2*)&sAk[(size_t)r0 * 68 + c] =
                        make_float2(acc[mt][nt][0], acc[mt][nt][1]);
                    *(float2*)&sAk[(size_t)(r0 + 8) * 68 + c] =
                        make_float2(acc[mt][nt][2], acc[mt][nt][3]);
                }
            }
        }
        __syncthreads();
        if (kq >= 2) {
            float* sAk = sAcc + (size_t)(kq - 2) * 64 * 68;
#pragma unroll
            for (int mt = 0; mt < 2; mt++) {
                int r0 = wm * 32 + mt * 16 + (lane >> 2);
#pragma unroll
                for (int nt = 0; nt < 4; nt++) {
                    int c = c0 + nt * 8;
                    float2 v0 = *(float2*)&sAk[(size_t)r0 * 68 + c];
                    float2 v1 = *(float2*)&sAk[(size_t)(r0 + 8) * 68 + c];
                    v0.x += acc[mt][nt][0]; v0.y += acc[mt][nt][1];
                    v1.x += acc[mt][nt][2]; v1.y += acc[mt][nt][3];
                    *(float2*)&sAk[(size_t)r0 * 68 + c]       = v0;
                    *(float2*)&sAk[(size_t)(r0 + 8) * 68 + c] = v1;
                }
            }
        }
        __syncthreads();

        // ---- activations + c update + coalesced h writes ----
        __half* hw = Hh + (size_t)sidx * BATCH * HID;
        float hv[2];
#pragma unroll
        for (int us = 0; us < 2; us++) {
            int uu = uug + us;
            float4 ga0 = *(const float4*)&sAcc[(size_t)eb * 68 + uu * 4];
            float4 ga1 = *(const float4*)&sAcc[(size_t)(64 * 68) + (size_t)eb * 68 + uu * 4];
            float gi = ga0.x + ga1.x + sG[((size_t)eb * 4 + 0) * 16 + uu];
            float gf = ga0.y + ga1.y + sG[((size_t)eb * 4 + 1) * 16 + uu];
            float gg = ga0.z + ga1.z + sG[((size_t)eb * 4 + 2) * 16 + uu];
            float go = ga0.w + ga1.w + sG[((size_t)eb * 4 + 3) * 16 + uu];
            float iv = 1.f / (1.f + expf(-gi));
            float fv = 1.f / (1.f + expf(-gf));
            float ov = 1.f / (1.f + expf(-go));
            float cn = fv * cst[us] + iv * tanhf(gg);
            cst[us] = cn;
            hv[us] = ov * tanhf(cn);
        }
        {
            int u = u0 + uug;
            *(__half2*)&hw[(size_t)eb * HID + u] = __floats2half2_rn(hv[0], hv[1]);
            if (out_sel) {
                float* h32r = H32 + (size_t)sidx * BATCH * HID;
                *(float2*)&h32r[(size_t)eb * HID + u] = make_float2(hv[0], hv[1]);
            }
        }

        // prefetch next step's gpre while waiting at the barrier
        if (ts + 1 < SEQ) {
            __syncthreads();   // all sG/sAcc reads done before overwrite
            issue_gpre(Gd + (size_t)(d ? SEQ - 2 - ts : ts + 1) * BATCH * G4);
        }

        grid_sync_d(d);
    }
}

// ---------------- output projection ----------------
__global__ void __launch_bounds__(256)
out_kernel(const float* __restrict__ Wout, const float* __restrict__ bout,
           float* __restrict__ out)
{
    __shared__ __align__(16) float hf[4][HID];
    __shared__ __align__(16) float hb[4][HID];
    const int tid   = threadIdx.x;
    const int pair0 = blockIdx.x * 4;

    for (int i = tid; i < 2048; i += 256) {
        int p   = i >> 9;
        int rem = i & 511;
        int sb  = pair0 + p;
        int r4  = rem & 255;
        const float* src = (rem < 256 ? g_Hf1 : g_Hb1) + (size_t)sb * HID;
        float4 v = ((const float4*)src)[r4];
        if (rem < 256) ((float4*)hf[p])[r4] = v;
        else           ((float4*)hb[p])[r4] = v;
    }
    __syncthreads();

    int p = tid >> 6;
    int o = tid & 63;
    if (o < OUTD) {
        int sb = pair0 + p;
        int s = sb >> 6, b = sb & 63;
        const float4* w0  = (const float4*)(Wout + (size_t)o * 2 * HID);
        const float4* w1  = w0 + 256;
        const float4* hf4 = (const float4*)hf[p];
        const float4* hb4 = (const float4*)hb[p];
        float acc = 0.f;
#pragma unroll 4
        for (int k = 0; k < 256; k++) {
            float4 a = hf4[k]; float4 w = w0[k];
            acc += a.x*w.x + a.y*w.y + a.z*w.z + a.w*w.w;
        }
#pragma unroll 4
        for (int k = 0; k < 256; k++) {
            float4 a = hb4[k]; float4 w = w1[k];
            acc += a.x*w.x + a.y*w.y + a.z*w.z + a.w*w.w;
        }
        out[((size_t)b * SEQ + s) * OUTD + o] = acc + bout[o];
    }
}

// ---------------- launch sequence ----------------
extern "C" void kernel_launch(void* const* d_in, const int* in_sizes, int n_in,
                              void* d_out, int out_size)
{
    const int*   src   = (const int*)  d_in[0];
    const float* emb   = (const float*)d_in[1];
    const float* Wih_f = (const float*)d_in[2];
    const float* Whh_f = (const float*)d_in[3];
    const float* b_f   = (const float*)d_in[4];
    const float* Wih_b = (const float*)d_in[5];
    const float* Whh_b = (const float*)d_in[6];
    const float* b_b   = (const float*)d_in[7];
    const float* Wout  = (const float*)d_in[8];
    const float* bout  = (const float*)d_in[9];
    float* out = (float*)d_out;
    (void)in_sizes; (void)n_in; (void)out_size;

    cudaFuncSetAttribute(gemm_fp16,
                         cudaFuncAttributeMaxDynamicSharedMemorySize, 3 * STAGE_BYTES);
    cudaFuncSetAttribute(lstm_recur_kernel,
                         cudaFuncAttributeMaxDynamicSharedMemorySize, RSMEM);

    embed_kernel<<<SEQ * BATCH * (EMB / 4) / 256, 256>>>(src, emb);

    dim3 ggrid(G4 / 128, (SEQ * BATCH) / 128);                 // (32, 256)
    const int convW_blocks = (G4 * 1024 / 4) / 256;            // 4096

    for (int l = 0; l < 2; l++) {
        size_t woff = (size_t)l * G4 * 1024;
        int a_f = (l == 0) ? 0 : 1;
        int a_b = (l == 0) ? 0 : 2;
        convW_kernel<<<convW_blocks, 256>>>(Wih_f + woff, 0);
        convW_kernel<<<convW_blocks, 256>>>(Wih_b + woff, 1);
        gemm_fp16<<<ggrid, 256, 3 * STAGE_BYTES>>>(a_f, 0, b_f + l * G4, 0);
        gemm_fp16<<<ggrid, 256, 3 * STAGE_BYTES>>>(a_b, 1, b_b + l * G4, 1);
        lstm_recur_kernel<<<NCTA, 512, RSMEM>>>(Whh_f + woff, Whh_b + woff, l);
    }

    out_kernel<<<(SEQ * BATCH) / 4, 256>>>(Wout, bout, out);
}